// round 10
// baseline (speedup 1.0000x reference)
#include <cuda_runtime.h>
#include <cuda_bf16.h>

// out[k][d] = mult_k * sum_i W_k[eb_input[i]][d]   (offsets mathematically dead:
// every index position lands in some bag and all bags are summed).
//
// hist : 1 u32 global RED per index, 1x int4/thread (measured 19.1us, ~floor).
//        Triggers programmatic launch completion early so the sweep can begin.
// sweep: PDL secondary. Prefetch table float4s into registers (count-independent,
//        uses DRAM/L2 bandwidth hist leaves idle), cudaGridDependencySynchronize,
//        then read counts and accumulate. Hot loop = exact R1 form (10.4us).
// final: separate 1-block kernel (fusing it measured slower twice).

#define MAX_EMB 2000000

__device__ unsigned int g_count[MAX_EMB];   // zero at load; sweep re-zeroes
__device__ double g_acc[9 * 64];            // padded accumulators

// ---------------------------------------------------------------------------
// Kernel 1: histogram. One int4 (4 indices) per thread, 4 REDs.
// ---------------------------------------------------------------------------
__global__ void k_hist(const int* __restrict__ idx, int n_idx) {
    cudaTriggerProgrammaticLaunchCompletion();   // let sweep grid start early
    int t = blockIdx.x * blockDim.x + threadIdx.x;
    int n4 = n_idx >> 2;
    if (t < n4) {
        int4 a = __ldcs((const int4*)idx + t);   // index stream: evict-first
        atomicAdd(&g_count[a.x], 1u);
        atomicAdd(&g_count[a.y], 1u);
        atomicAdd(&g_count[a.z], 1u);
        atomicAdd(&g_count[a.w], 1u);
    }
    if (blockIdx.x == 0) {                       // scalar tail
        int rem = n_idx & 3;
        if ((int)threadIdx.x < rem)
            atomicAdd(&g_count[idx[(n4 << 2) + threadIdx.x]], 1u);
    }
}

// ---------------------------------------------------------------------------
// Kernel 2: weighted sweep (R1 hot loop) with PDL prefetch.
// ---------------------------------------------------------------------------
__global__ void k_sweep(const float* __restrict__ W0,
                        const float* __restrict__ W1,
                        const float* __restrict__ W2,
                        int num_emb) {
    int t = blockIdx.x * blockDim.x + threadIdx.x;
    int r0 = t * 4;
    bool full = (r0 + 4 <= num_emb);

    // ---- count-independent prefetch: 3 tables x 3 float4 into registers ----
    float4 a0, b0, d0, a1, b1, d1, a2, b2, d2;
    if (full) {
        const float4* V0 = (const float4*)W0 + 3 * t;
        const float4* V1 = (const float4*)W1 + 3 * t;
        const float4* V2 = (const float4*)W2 + 3 * t;
        a0 = __ldg(V0 + 0); b0 = __ldg(V0 + 1); d0 = __ldg(V0 + 2);
        a1 = __ldg(V1 + 0); b1 = __ldg(V1 + 1); d1 = __ldg(V1 + 2);
        a2 = __ldg(V2 + 0); b2 = __ldg(V2 + 1); d2 = __ldg(V2 + 2);
    }

    // ---- wait for histogram grid to complete (PDL dependency) ----
    cudaGridDependencySynchronize();

    float acc[9];
#pragma unroll
    for (int k = 0; k < 9; k++) acc[k] = 0.0f;

    if (full) {
        uint4 c4 = *(const uint4*)&g_count[r0];
        *(uint4*)&g_count[r0] = make_uint4(0u, 0u, 0u, 0u);   // re-init for replay
        float c0 = (float)c4.x, c1 = (float)c4.y, c2 = (float)c4.z, c3 = (float)c4.w;

        // rows: r0: a.x a.y a.z | r0+1: a.w b.x b.y | r0+2: b.z b.w d.x | r0+3: d.y d.z d.w
        acc[0] += c0 * a0.x + c1 * a0.w + c2 * b0.z + c3 * d0.y;
        acc[1] += c0 * a0.y + c1 * b0.x + c2 * b0.w + c3 * d0.z;
        acc[2] += c0 * a0.z + c1 * b0.y + c2 * d0.x + c3 * d0.w;
        acc[3] += c0 * a1.x + c1 * a1.w + c2 * b1.z + c3 * d1.y;
        acc[4] += c0 * a1.y + c1 * b1.x + c2 * b1.w + c3 * d1.z;
        acc[5] += c0 * a1.z + c1 * b1.y + c2 * d1.x + c3 * d1.w;
        acc[6] += c0 * a2.x + c1 * a2.w + c2 * b2.z + c3 * d2.y;
        acc[7] += c0 * a2.y + c1 * b2.x + c2 * b2.w + c3 * d2.z;
        acc[8] += c0 * a2.z + c1 * b2.y + c2 * d2.x + c3 * d2.w;
    } else if (r0 < num_emb) {
        for (int r = r0; r < num_emb; r++) {
            float c = (float)g_count[r];
            g_count[r] = 0u;
            const float* Ws[3] = {W0, W1, W2};
#pragma unroll
            for (int k = 0; k < 3; k++) {
                acc[3 * k + 0] += c * Ws[k][3 * r + 0];
                acc[3 * k + 1] += c * Ws[k][3 * r + 1];
                acc[3 * k + 2] += c * Ws[k][3 * r + 2];
            }
        }
    }

    // warp reduction
    unsigned lane = threadIdx.x & 31u;
    unsigned warp = threadIdx.x >> 5;
#pragma unroll
    for (int k = 0; k < 9; k++) {
#pragma unroll
        for (int o = 16; o > 0; o >>= 1)
            acc[k] += __shfl_down_sync(0xffffffffu, acc[k], o);
    }

    __shared__ float s_red[8][9];
    if (lane == 0) {
#pragma unroll
        for (int k = 0; k < 9; k++) s_red[warp][k] = acc[k];
    }
    __syncthreads();

    if (threadIdx.x < 9) {
        double s = 0.0;
#pragma unroll
        for (int w = 0; w < 8; w++) s += (double)s_red[w][threadIdx.x];
        atomicAdd(&g_acc[threadIdx.x * 64], s);
    }
}

// ---------------------------------------------------------------------------
// Kernel 3: scale, write output, re-zero accumulators for next replay.
// ---------------------------------------------------------------------------
__global__ void k_final(float* __restrict__ out) {
    int i = threadIdx.x;
    if (i < 9) {
        const float mult[3] = {5.0f, 10.0f, 6.0f};
        double v = g_acc[i * 64];
        g_acc[i * 64] = 0.0;
        out[i] = (float)((double)mult[i / 3] * v);
    }
}

// ---------------------------------------------------------------------------
extern "C" void kernel_launch(void* const* d_in, const int* in_sizes, int n_in,
                              void* d_out, int out_size) {
    const int*   idx = (const int*)d_in[0];
    // d_in[1] = eb_offset : mathematically unused
    const float* W0  = (const float*)d_in[2];
    const float* W1  = (const float*)d_in[3];
    const float* W2  = (const float*)d_in[4];
    int n_idx   = in_sizes[0];
    int num_emb = in_sizes[2] / 3;

    int n4 = n_idx >> 2;
    int hist_blocks = (n4 + 255) / 256;
    if (hist_blocks < 1) hist_blocks = 1;
    k_hist<<<hist_blocks, 256>>>(idx, n_idx);

    // sweep: PDL launch — overlaps its table prefetch with hist's atomic drain
    int sweep_threads = (num_emb + 3) / 4;
    int sweep_blocks = (sweep_threads + 255) / 256;
    if (sweep_blocks < 1) sweep_blocks = 1;
    {
        cudaLaunchConfig_t cfg = {};
        cfg.gridDim  = dim3((unsigned)sweep_blocks, 1, 1);
        cfg.blockDim = dim3(256, 1, 1);
        cfg.dynamicSmemBytes = 0;
        cfg.stream = 0;   // legacy default stream (same one the harness captures)
        cudaLaunchAttribute attr[1];
        attr[0].id = cudaLaunchAttributeProgrammaticStreamSerialization;
        attr[0].val.programmaticStreamSerializationAllowed = 1;
        cfg.attrs = attr;
        cfg.numAttrs = 1;
        cudaLaunchKernelEx(&cfg, k_sweep, W0, W1, W2, num_emb);
    }

    k_final<<<1, 32>>>((float*)d_out);
}

// round 12
// speedup vs baseline: 1.2345x; 1.2345x over previous
#include <cuda_runtime.h>
#include <cuda_bf16.h>

// out[k][d] = mult_k * sum_i W_k[eb_input[i]][d]   (offsets mathematically dead:
// every index position lands in some bag and all bags are summed).
//
// Best-measured composition (no experiments this round):
//  hist : 1x int4/thread, 4x u32 REDG, __ldcs index stream   (measured 19.1us)
//  sweep: R1 hot loop — 4 rows/thread, uint4 count read+zero,
//         3x float4 __ldg per table, tables L2-warm across replays (10.4us)
//  final: separate 1-block kernel (every fusion attempt measured slower)

#define MAX_EMB 2000000

// 8MB u32 counts. Zeroed at load; sweep re-zeroes after reading -> clean state
// for every graph replay.
__device__ unsigned int g_count[MAX_EMB];
// 9 double accumulators padded to 512B stride (distinct L2 slices).
__device__ double g_acc[9 * 64];

// ---------------------------------------------------------------------------
// Kernel 1: histogram. One int4 (4 indices) per thread, 4 REDs.
// ---------------------------------------------------------------------------
__global__ void k_hist(const int* __restrict__ idx, int n_idx) {
    int t = blockIdx.x * blockDim.x + threadIdx.x;
    int n4 = n_idx >> 2;
    if (t < n4) {
        int4 a = __ldcs((const int4*)idx + t);   // index stream: evict-first
        atomicAdd(&g_count[a.x], 1u);
        atomicAdd(&g_count[a.y], 1u);
        atomicAdd(&g_count[a.z], 1u);
        atomicAdd(&g_count[a.w], 1u);
    }
    if (blockIdx.x == 0) {                       // scalar tail
        int rem = n_idx & 3;
        if ((int)threadIdx.x < rem)
            atomicAdd(&g_count[idx[(n4 << 2) + threadIdx.x]], 1u);
    }
}

// ---------------------------------------------------------------------------
// Kernel 2: weighted sweep — exact R1 hot loop (measured 10.4us).
// ---------------------------------------------------------------------------
__global__ void k_sweep(const float* __restrict__ W0,
                        const float* __restrict__ W1,
                        const float* __restrict__ W2,
                        int num_emb) {
    int t = blockIdx.x * blockDim.x + threadIdx.x;
    int r0 = t * 4;

    float acc[9];
#pragma unroll
    for (int k = 0; k < 9; k++) acc[k] = 0.0f;

    if (r0 + 4 <= num_emb) {
        uint4 c4 = *(const uint4*)&g_count[r0];
        *(uint4*)&g_count[r0] = make_uint4(0u, 0u, 0u, 0u);   // re-init for replay
        float c0 = (float)c4.x, c1 = (float)c4.y, c2 = (float)c4.z, c3 = (float)c4.w;

        const float* Ws[3] = {W0, W1, W2};
#pragma unroll
        for (int k = 0; k < 3; k++) {
            const float4* Wv = (const float4*)Ws[k] + 3 * t;   // 12 floats = 4 rows
            float4 a = __ldg(Wv + 0);
            float4 b = __ldg(Wv + 1);
            float4 d = __ldg(Wv + 2);
            // rows: r0: a.x a.y a.z | r0+1: a.w b.x b.y | r0+2: b.z b.w d.x | r0+3: d.y d.z d.w
            acc[3 * k + 0] += c0 * a.x + c1 * a.w + c2 * b.z + c3 * d.y;
            acc[3 * k + 1] += c0 * a.y + c1 * b.x + c2 * b.w + c3 * d.z;
            acc[3 * k + 2] += c0 * a.z + c1 * b.y + c2 * d.x + c3 * d.w;
        }
    } else if (r0 < num_emb) {
        for (int r = r0; r < num_emb; r++) {
            float c = (float)g_count[r];
            g_count[r] = 0u;
            const float* Ws[3] = {W0, W1, W2};
#pragma unroll
            for (int k = 0; k < 3; k++) {
                acc[3 * k + 0] += c * Ws[k][3 * r + 0];
                acc[3 * k + 1] += c * Ws[k][3 * r + 1];
                acc[3 * k + 2] += c * Ws[k][3 * r + 2];
            }
        }
    }

    // warp reduction
    unsigned lane = threadIdx.x & 31u;
    unsigned warp = threadIdx.x >> 5;
#pragma unroll
    for (int k = 0; k < 9; k++) {
#pragma unroll
        for (int o = 16; o > 0; o >>= 1)
            acc[k] += __shfl_down_sync(0xffffffffu, acc[k], o);
    }

    __shared__ float s_red[8][9];
    if (lane == 0) {
#pragma unroll
        for (int k = 0; k < 9; k++) s_red[warp][k] = acc[k];
    }
    __syncthreads();

    if (threadIdx.x < 9) {
        double s = 0.0;
#pragma unroll
        for (int w = 0; w < 8; w++) s += (double)s_red[w][threadIdx.x];
        atomicAdd(&g_acc[threadIdx.x * 64], s);
    }
}

// ---------------------------------------------------------------------------
// Kernel 3: scale, write output, re-zero accumulators for next replay.
// ---------------------------------------------------------------------------
__global__ void k_final(float* __restrict__ out) {
    int i = threadIdx.x;
    if (i < 9) {
        const float mult[3] = {5.0f, 10.0f, 6.0f};
        double v = g_acc[i * 64];
        g_acc[i * 64] = 0.0;
        out[i] = (float)((double)mult[i / 3] * v);
    }
}

// ---------------------------------------------------------------------------
extern "C" void kernel_launch(void* const* d_in, const int* in_sizes, int n_in,
                              void* d_out, int out_size) {
    const int*   idx = (const int*)d_in[0];
    // d_in[1] = eb_offset : mathematically unused
    const float* W0  = (const float*)d_in[2];
    const float* W1  = (const float*)d_in[3];
    const float* W2  = (const float*)d_in[4];
    int n_idx   = in_sizes[0];
    int num_emb = in_sizes[2] / 3;

    int n4 = n_idx >> 2;
    int hist_blocks = (n4 + 255) / 256;
    if (hist_blocks < 1) hist_blocks = 1;
    k_hist<<<hist_blocks, 256>>>(idx, n_idx);

    int sweep_threads = (num_emb + 3) / 4;
    int sweep_blocks = (sweep_threads + 255) / 256;
    if (sweep_blocks < 1) sweep_blocks = 1;
    k_sweep<<<sweep_blocks, 256>>>(W0, W1, W2, num_emb);

    k_final<<<1, 32>>>((float*)d_out);
}